// round 11
// baseline (speedup 1.0000x reference)
#include <cuda_runtime.h>

// MDPPInitEmbedding — two-kernel split.
// K1: g_vec prep + spatial-binned nearest-probe search -> g_md
// K2: high-occupancy rank-3 epilogue: out = x*v0 + y*v1 + md*v2 + c
// Launch boundary = producer/consumer sync (no flags).

#define BB   16
#define NN   2048
#define EE   256
#define TILE 256
#define G    16
#define GC   (G * G)
#define HINV 16.0f
#define HH   (1.0f / 16.0f)
#define FBIG 3.0e38f

__device__ float g_vec[4 * EE];     // [v0 | v1 | v2 | c]
__device__ float g_md[BB * NN];     // min distances (scratch)

// ---------------------------------------------------------------------------
// K1: 128 CTAs (16 batches x 8 node-tiles) x 512 threads.
// ---------------------------------------------------------------------------
__global__ __launch_bounds__(512, 1)
void search_kernel(const float* __restrict__ locs,
                   const int*   __restrict__ probe,
                   const float* __restrict__ Wn,
                   const float* __restrict__ bn,
                   const float* __restrict__ Wd,
                   const float* __restrict__ bd,
                   const float* __restrict__ Wo,
                   const float* __restrict__ bo) {
    __shared__ float2 stash[NN];       // 16 KB: all locs of this batch
    __shared__ float2 sorted[NN];      // 16 KB: binned probes
    __shared__ int    s_cnt[GC], s_off[GC], s_cur[GC];   // 3 KB
    __shared__ float  sred[128];
    __shared__ int    s_wsum[16];

    int tid  = threadIdx.x;
    int bx   = blockIdx.x;
    int b    = bx >> 3;
    int n0   = (bx & 7) * TILE;
    int lane = tid & 31;
    int wid  = tid >> 5;

    // ---- Prep: g_vec columns {2bx, 2bx+1}; 512 rows of W_out, 1 row/thread
    {
        int half = tid >> 8;                  // 0: rows<256, 1: rows>=256
        int rr   = tid & 255;
        float2 w = *reinterpret_cast<const float2*>(&Wo[(half * 256 + rr) * EE + 2 * bx]);
        float s0, s1, s2, s3, sc0, sc1;
        if (half == 0) {
            float wn0 = Wn[rr], wn1 = Wn[EE + rr], bv = bn[rr];
            s0 = wn0 * w.x; s1 = wn0 * w.y;
            s2 = wn1 * w.x; s3 = wn1 * w.y;
            sc0 = bv * w.x; sc1 = bv * w.y;
        } else {
            float wd = Wd[rr], bv = bd[rr];
            s0 = wd * w.x; s1 = wd * w.y;     // goes to v2 slot for half==1
            s2 = 0.f;      s3 = 0.f;
            sc0 = bv * w.x; sc1 = bv * w.y;
        }
        #pragma unroll
        for (int off = 16; off >= 1; off >>= 1) {
            s0  += __shfl_xor_sync(0xffffffffu, s0,  off);
            s1  += __shfl_xor_sync(0xffffffffu, s1,  off);
            s2  += __shfl_xor_sync(0xffffffffu, s2,  off);
            s3  += __shfl_xor_sync(0xffffffffu, s3,  off);
            sc0 += __shfl_xor_sync(0xffffffffu, sc0, off);
            sc1 += __shfl_xor_sync(0xffffffffu, sc1, off);
        }
        if (lane == 0) {
            sred[wid * 8 + 0] = s0;  sred[wid * 8 + 1] = s1;
            sred[wid * 8 + 2] = s2;  sred[wid * 8 + 3] = s3;
            sred[wid * 8 + 4] = sc0; sred[wid * 8 + 5] = sc1;
        }
        __syncthreads();
        if (tid < 8) {
            int slot = tid >> 1, col = tid & 1;
            float acc = 0.f;
            if (slot == 0) {                       // v0: warps 0..7 s0/s1
                for (int w8 = 0; w8 < 8; w8++)   acc += sred[w8 * 8 + 0 + col];
            } else if (slot == 1) {                // v1: warps 0..7 s2/s3
                for (int w8 = 0; w8 < 8; w8++)   acc += sred[w8 * 8 + 2 + col];
            } else if (slot == 2) {                // v2: warps 8..15 s0/s1
                for (int w8 = 8; w8 < 16; w8++)  acc += sred[w8 * 8 + 0 + col];
            } else {                               // c: all warps sc + bo
                acc = bo[2 * bx + col];
                for (int w8 = 0; w8 < 16; w8++)  acc += sred[w8 * 8 + 4 + col];
            }
            g_vec[slot * EE + 2 * bx + col] = acc;
        }
        // __syncthreads below (bin phase) also retires sred before reuse-free
    }

    // ---- Phase 1: bin probes (counting sort into 16x16 grid)
    if (tid < GC) s_cnt[tid] = 0;
    __syncthreads();

    const float2* lb = reinterpret_cast<const float2*>(locs) + (size_t)b * NN;
    const int*    pb = probe + (size_t)b * NN;

    #pragma unroll
    for (int it = 0; it < NN / 512; it++) {
        int i = it * 512 + tid;
        float2 xy = lb[i];
        stash[i] = xy;
        if (pb[i]) {
            int cxp = min(G - 1, max(0, (int)(xy.x * HINV)));
            int cyp = min(G - 1, max(0, (int)(xy.y * HINV)));
            atomicAdd(&s_cnt[cyp * G + cxp], 1);
        }
    }
    __syncthreads();

    // exclusive prefix sum over 256 cells (first 8 warps)
    if (tid < GC) {
        int v = s_cnt[tid];
        int incl = v;
        #pragma unroll
        for (int off = 1; off < 32; off <<= 1) {
            int nv = __shfl_up_sync(0xffffffffu, incl, off);
            if (lane >= off) incl += nv;
        }
        if (lane == 31) s_wsum[wid] = incl;
        __syncthreads();
        if (wid == 0) {
            int x = (lane < 8) ? s_wsum[lane] : 0;
            int sc = x;
            #pragma unroll
            for (int off = 1; off < 8; off <<= 1) {
                int nv = __shfl_up_sync(0xffffffffu, sc, off);
                if (lane >= off) sc += nv;
            }
            if (lane < 8) s_wsum[lane] = sc - x;
        }
        __syncthreads();
        int excl = s_wsum[wid] + incl - v;
        s_off[tid] = excl;
        s_cur[tid] = excl;
    } else {
        __syncthreads();
        __syncthreads();
    }
    __syncthreads();

    // scatter probes into bins (locs from smem stash)
    #pragma unroll
    for (int it = 0; it < NN / 512; it++) {
        int i = it * 512 + tid;
        if (pb[i]) {
            float2 xy = stash[i];
            int cxp = min(G - 1, max(0, (int)(xy.x * HINV)));
            int cyp = min(G - 1, max(0, (int)(xy.y * HINV)));
            int pos = atomicAdd(&s_cur[cyp * G + cxp], 1);
            sorted[pos] = xy;
        }
    }
    __syncthreads();

    // ---- Phase 2: ring search; threads 0..255 own one node each
    if (tid < TILE) {
        float2 my = stash[n0 + tid];
        int cx = min(G - 1, max(0, (int)(my.x * HINV)));
        int cy = min(G - 1, max(0, (int)(my.y * HINV)));
        float best = FBIG;

        #pragma unroll 1
        for (int R = 0; R < G; R++) {
            int xa = max(cx - R, 0), xb = min(cx + R, G - 1);
            int ya = max(cy - R, 0), yb = min(cy + R, G - 1);
            #pragma unroll 1
            for (int gy = ya; gy <= yb; gy++) {
                bool edge_row = (gy == cy - R) || (gy == cy + R);
                int rowb = gy * G;
                #pragma unroll 1
                for (int gx = xa; gx <= xb; gx++) {
                    if (!edge_row && gx != cx - R && gx != cx + R) continue;
                    int c = rowb + gx;
                    int k = s_off[c], e = k + s_cnt[c];
                    for (; k < e; k++) {
                        float2 p = sorted[k];
                        float dx = p.x - my.x, dy = p.y - my.y;
                        best = fminf(best, fmaf(dx, dx, dy * dy));
                    }
                }
            }
            float bnd = (float)R * HH;
            if (best <= bnd * bnd) break;   // unscanned cells are >= R*h away
        }
        g_md[b * NN + n0 + tid] = sqrtf(best);  // exact 0 for self-probe nodes
    }
}

// ---------------------------------------------------------------------------
// K2: epilogue. 1024 CTAs x 256 threads, 32 nodes/CTA, no smem.
// thread: q = tid&63 (e-quad), wn = tid>>6 (node offset), 8 iters.
// ---------------------------------------------------------------------------
__global__ void epilogue_kernel(const float* __restrict__ locs,
                                float* __restrict__ out) {
    int tid = threadIdx.x;
    int bx  = blockIdx.x;
    int b   = bx >> 6;
    int n0  = (bx & 63) * 32;
    int q   = tid & 63;
    int wn  = tid >> 6;

    float4 v0 = *reinterpret_cast<const float4*>(&g_vec[0 * EE + q * 4]);
    float4 v1 = *reinterpret_cast<const float4*>(&g_vec[1 * EE + q * 4]);
    float4 v2 = *reinterpret_cast<const float4*>(&g_vec[2 * EE + q * 4]);
    float4 cc = *reinterpret_cast<const float4*>(&g_vec[3 * EE + q * 4]);

    const float2* lb = reinterpret_cast<const float2*>(locs) + (size_t)b * NN + n0;
    const float*  mb = g_md + (size_t)b * NN + n0;
    float4* ob = reinterpret_cast<float4*>(out) + (size_t)(b * NN + n0) * (EE / 4);

    #pragma unroll
    for (int n = wn; n < 32; n += 4) {
        float2 xy = lb[n];
        float  md = mb[n];
        float4 o;
        o.x = fmaf(xy.x, v0.x, fmaf(xy.y, v1.x, fmaf(md, v2.x, cc.x)));
        o.y = fmaf(xy.x, v0.y, fmaf(xy.y, v1.y, fmaf(md, v2.y, cc.y)));
        o.z = fmaf(xy.x, v0.z, fmaf(xy.y, v1.z, fmaf(md, v2.z, cc.z)));
        o.w = fmaf(xy.x, v0.w, fmaf(xy.y, v1.w, fmaf(md, v2.w, cc.w)));
        ob[(size_t)n * (EE / 4) + q] = o;
    }
}

// ---------------------------------------------------------------------------
extern "C" void kernel_launch(void* const* d_in, const int* in_sizes, int n_in,
                              void* d_out, int out_size) {
    const float* locs  = (const float*)d_in[0];
    const int*   probe = (const int*)d_in[1];
    const float* Wn    = (const float*)d_in[2];
    const float* bn    = (const float*)d_in[3];
    const float* Wd    = (const float*)d_in[4];
    const float* bd    = (const float*)d_in[5];
    const float* Wo    = (const float*)d_in[6];
    const float* bo    = (const float*)d_in[7];
    float*       out   = (float*)d_out;

    search_kernel<<<BB * (NN / TILE), 512>>>(locs, probe, Wn, bn, Wd, bd, Wo, bo);
    epilogue_kernel<<<BB * 64, 256>>>(locs, out);
}